// round 15
// baseline (speedup 1.0000x reference)
#include <cuda_runtime.h>
#include <cuda_fp16.h>
#include <math.h>
#include <stdint.h>

#define DIMC 384
#define HIDC 1536
#define MMAX 16384

// ---------------- scratch (device globals; no allocation allowed) ----------
__device__ __half g_y [MMAX * DIMC];            // LN output (fp16)
__device__ __half g_qb[MMAX * DIMC];            // q after rope (fp16)
__device__ __half g_h [MMAX * HIDC];            // titan hidden; later reused as
                                                // 2x fp32 split-K partials
__device__ float  g_xn[MMAX * DIMC];            // x + titan branch (fp32)
__device__ __half g_hc[(long)MMAX * 3 * HIDC];  // cms hidden concat (fp16)
__device__ __half g_tw2h[HIDC * DIMC];          // titan_w2[4] as fp16
__device__ __half g_owT [DIMC * DIMC];          // out_w^T fp16
__device__ __half g_qwT [DIMC * DIMC];          // q_w^T
__device__ __half g_tw1T[HIDC * DIMC];          // titan_w1[4]^T
__device__ __half g_w2fT[DIMC * HIDC];          // (titan_w2[4] @ out_w)^T fp16
__device__ __half g_cw1T[3L * HIDC * DIMC];     // cms_w1^T stacked [4608,384]
__device__ __half g_cw2T[(long)DIMC * 3 * HIDC];// cms_w2^T [384,4608]
__device__ float g_b2f[DIMC];
__device__ float g_b2s[DIMC];

// ---------------- helpers ---------------------------------------------------
__device__ __forceinline__ uint32_t smem_u32(const void* p) {
    uint32_t a;
    asm("{ .reg .u64 t; cvta.to.shared.u64 t, %1; cvt.u32.u64 %0, t; }"
        : "=r"(a) : "l"(p));
    return a;
}
// fast gelu: tanh formulation + tanh.approx.f32
__device__ __forceinline__ float gelu_fast(float v) {
    float u = v * (1.0f + 0.044715f * v * v) * 0.7978845608028654f;
    float t;
    asm("tanh.approx.f32 %0, %1;" : "=f"(t) : "f"(u));
    return 0.5f * v * (1.0f + t);
}
__device__ __forceinline__ void cp16(uint32_t s, const void* g) {
    asm volatile("cp.async.cg.shared.global [%0], [%1], 16;"
                 :: "r"(s), "l"(g) : "memory");
}
__device__ __forceinline__ void cp_commit() {
    asm volatile("cp.async.commit_group;" ::: "memory");
}
template <int N> __device__ __forceinline__ void cp_wait() {
    asm volatile("cp.async.wait_group %0;" :: "n"(N) : "memory");
}
__device__ __forceinline__ void ldsm4(uint32_t& r0, uint32_t& r1,
                                      uint32_t& r2, uint32_t& r3, uint32_t a) {
    asm volatile("ldmatrix.sync.aligned.m8n8.x4.shared.b16 {%0,%1,%2,%3}, [%4];"
                 : "=r"(r0), "=r"(r1), "=r"(r2), "=r"(r3) : "r"(a));
}
__device__ __forceinline__ void hmma(float* c, const uint32_t* a, const uint32_t* b) {
    asm volatile(
        "mma.sync.aligned.m16n8k16.row.col.f32.f16.f16.f32 "
        "{%0,%1,%2,%3}, {%4,%5,%6,%7}, {%8,%9}, {%0,%1,%2,%3};"
        : "+f"(c[0]), "+f"(c[1]), "+f"(c[2]), "+f"(c[3])
        : "r"(a[0]), "r"(a[1]), "r"(a[2]), "r"(a[3]), "r"(b[0]), "r"(b[1]));
}

#define SWZ(off) ((off) ^ (((off) >> 3) & 0x70))
#define STAGES 3

// ---------------- tensor-core GEMM: C[M,N] = A[M,K] @ Bt[N,K]^T -------------
// Block tile (64*WARPS_M)x(WARP_N*WARPS_N), BK=64 fp16 (SW128), 3-stage
// cp.async pipe, 128 threads.
//   S: WARPS_M=1,WARPS_N=4,WARP_N=32 -> 64x128 tile, 3 CTAs/SM (small N)
//   F: WARPS_M=2,WARPS_N=2,WARP_N=64 -> 128x128 tile, warp 64x64, 2 CTAs/SM
// EPI: 0 none, 1 gelu(+bias), 2 (+bias)(+res), 3 rope3d,
//      4 split-K partial (blockIdx.z selects K-half; raw fp32 out to
//        partial buffer z, no bias/res).   OUTH: 1 = fp16 out.

template <int EPI, int OUTH, int WARPS_M, int WARPS_N, int WARP_N, int LDA, int LDB>
__global__ void __launch_bounds__(32 * WARPS_M * WARPS_N, WARP_N == 64 ? 2 : 3)
tgemm(const __half* __restrict__ A,
      const __half* __restrict__ Bt,
      const float* __restrict__ bias,
      const float* __restrict__ res, int ldres,
      void* __restrict__ Cout, int ldc, int K,
      const int* __restrict__ pT, const int* __restrict__ pH,
      const int* __restrict__ pW) {
    constexpr int BMV = 64 * WARPS_M;
    constexpr int BNV = WARP_N * WARPS_N;
    constexpr int THREADS = 32 * WARPS_M * WARPS_N;
    constexpr int STG = (BMV + BNV) * 128;      // bytes per stage (1024-mult)
    constexpr int ROWSTEP = THREADS / 8;        // rows per load slot
    constexpr int NA = BMV / ROWSTEP;           // A load slots per thread
    constexpr int NB = BNV / ROWSTEP;           // B load slots per thread
    constexpr int NBF = WARP_N / 16;            // B ldsm4 per kk
    constexpr int NT = WARP_N / 8;              // n-subtiles per warp
    extern __shared__ char dsm[];
    const int tid  = threadIdx.x;
    const int wid  = tid >> 5;
    const int lane = tid & 31;
    const int wm = wid / WARPS_N;
    const int wn = wid % WARPS_N;
    const uint32_t sbase = (smem_u32(dsm) + 1023u) & ~1023u;   // 1024-aligned
    const uint32_t send  = sbase + 3 * STG;

    float acc[4][NT][4];
#pragma unroll
    for (int i = 0; i < 4; i++)
#pragma unroll
        for (int j = 0; j < NT; j++)
#pragma unroll
            for (int k = 0; k < 4; k++) acc[i][j][k] = 0.f;

    // ---- load-slot addressing (slot-0 pointer + compile-time slot offsets) --
    const int lrow = tid >> 3, lc16 = tid & 7;
    long zoff = 0;
    if (EPI == 4) zoff = (long)blockIdx.z * K;   // split-K half offset
    const __half* pA = A  + (long)blockIdx.y * BMV * LDA + zoff + (long)lrow * LDA + lc16 * 8;
    const __half* pB = Bt + (long)blockIdx.x * BNV * LDB + zoff + (long)lrow * LDB + lc16 * 8;
    uint32_t a_soff[NA];
#pragma unroll
    for (int p = 0; p < NA; p++)
        a_soff[p] = SWZ((lrow + p * ROWSTEP) * 128 + lc16 * 16);
    uint32_t b_soff[NB];
#pragma unroll
    for (int p = 0; p < NB; p++)
        b_soff[p] = BMV * 128 + SWZ((lrow + p * ROWSTEP) * 128 + lc16 * 16);

    auto load_chunk = [&](uint32_t sb, const __half* cA, const __half* cB) {
#pragma unroll
        for (int p = 0; p < NA; p++)
            cp16(sb + a_soff[p], cA + (long)p * ROWSTEP * LDA);
#pragma unroll
        for (int p = 0; p < NB; p++)
            cp16(sb + b_soff[p], cB + (long)p * ROWSTEP * LDB);
        cp_commit();
    };

    const int nch = K >> 6;                     // always >= 3 here
    load_chunk(sbase, pA, pB);
    load_chunk(sbase + STG, pA + 64, pB + 64);
    pA += 128; pB += 128;
    uint32_t sb_pre = sbase + 2 * STG;          // stage for next prefetch
    uint32_t sA = sbase;                        // stage being consumed

    // ---- hoisted fragment addressing ----
    const int a_row  = wm * 64 + (lane & 7) + (((lane >> 3) & 1) << 3);
    const int a_colb = (lane >> 4) * 16;
    const int b_row  = wn * WARP_N + (lane & 7) + ((lane >> 4) << 3);
    const int b_colb = ((lane >> 3) & 1) * 16;
    uint32_t a_base[4], b_base[NBF];
#pragma unroll
    for (int mt = 0; mt < 4; mt++)
        a_base[mt] = SWZ((a_row + mt * 16) * 128 + a_colb);
#pragma unroll
    for (int nb = 0; nb < NBF; nb++)
        b_base[nb] = BMV * 128 + SWZ((b_row + nb * 16) * 128 + b_colb);

    for (int c = 0; c < nch; c++) {
        if (c + STAGES - 1 < nch) cp_wait<STAGES - 2>();
        else                      cp_wait<0>();
        __syncthreads();   // also protects the buffer reused by prefetch below
        if (c + STAGES - 1 < nch) {
            load_chunk(sb_pre, pA, pB);
            pA += 64; pB += 64;
            sb_pre += STG; if (sb_pre == send) sb_pre = sbase;
        }

        uint32_t aa[4], bb[NBF];
#pragma unroll
        for (int mt = 0; mt < 4; mt++) aa[mt] = sA + a_base[mt];
#pragma unroll
        for (int nb = 0; nb < NBF; nb++) bb[nb] = sA + b_base[nb];
        sA += STG; if (sA == send) sA = sbase;

#pragma unroll
        for (int kk = 0; kk < 4; kk++) {
            const uint32_t kx = kk << 5;
            uint32_t afr[4][4];
#pragma unroll
            for (int mt = 0; mt < 4; mt++)
                ldsm4(afr[mt][0], afr[mt][1], afr[mt][2], afr[mt][3], aa[mt] ^ kx);
            uint32_t bfr[NT][2];
#pragma unroll
            for (int nb = 0; nb < NBF; nb++) {
                uint32_t r0, r1, r2, r3;
                ldsm4(r0, r1, r2, r3, bb[nb] ^ kx);
                bfr[nb * 2][0] = r0; bfr[nb * 2][1] = r1;
                bfr[nb * 2 + 1][0] = r2; bfr[nb * 2 + 1][1] = r3;
            }
#pragma unroll
            for (int mt = 0; mt < 4; mt++)
#pragma unroll
                for (int nt = 0; nt < NT; nt++)
                    hmma(acc[mt][nt], afr[mt], bfr[nt]);
        }
    }

    // ---- epilogue ----
    const int g = lane >> 2, tig = lane & 3;
    const long row0 = (long)blockIdx.y * BMV + wm * 64;
    const int colb  = blockIdx.x * BNV + wn * WARP_N;
    float* Cf = (float*)Cout;
    if (EPI == 4)   // partial buffer z
        Cf += (long)blockIdx.z * gridDim.y * (long)BMV * ldc;
    __half* Ch = (__half*)Cout;

    int rT = 0, rH = 0, rW = 0;
    if (EPI == 3) { rT = __ldg(pT); rH = __ldg(pH); rW = __ldg(pW); }

#pragma unroll
    for (int mt = 0; mt < 4; mt++) {
#pragma unroll
        for (int h = 0; h < 2; h++) {
            long row = row0 + mt * 16 + g + h * 8;
            float tp = 0.f, hp = 0.f, wp = 0.f;
            if (EPI == 3) {
                int Nn = rT * rH * rW;
                int n = (int)(row % Nn);
                int HW = rH * rW;
                tp = (float)(n / HW);
                int rem = n % HW;
                hp = (float)(rem / rW);
                wp = (float)(rem % rW);
            }
#pragma unroll
            for (int nt = 0; nt < NT; nt++) {
                int col = colb + nt * 8 + tig * 2;
                float v0 = acc[mt][nt][2 * h];
                float v1 = acc[mt][nt][2 * h + 1];
                if (EPI == 1 || EPI == 2) {
                    float2 bv = *(const float2*)(bias + col);
                    v0 += bv.x; v1 += bv.y;
                }
                if (EPI == 1) { v0 = gelu_fast(v0); v1 = gelu_fast(v1); }
                if (EPI == 2) {
                    float2 r = *(const float2*)(res + row * (long)ldres + col);
                    v0 += r.x; v1 += r.y;
                }
                if (EPI == 3) {
                    int hd = col % 24;
                    int ch = hd >> 3;
                    int jj = (hd & 7) >> 1;
                    float pos = (ch == 0) ? tp : ((ch == 1) ? hp : wp);
                    const float tbl[4] = {1.0f, 0.1f, 0.01f, 0.001f};
                    float ang = pos * tbl[jj];
                    float sn, cs;
                    sincosf(ang, &sn, &cs);
                    float n0 = v0 * cs - v1 * sn;
                    float n1 = v0 * sn + v1 * cs;
                    v0 = n0; v1 = n1;
                }
                if (OUTH) {
                    __half2 t = __floats2half2_rn(v0, v1);
                    *(__half2*)(Ch + row * (long)ldc + col) = t;
                } else {
                    *(float2*)(Cf + row * (long)ldc + col) = make_float2(v0, v1);
                }
            }
        }
    }
}

// ---------------- split-K combine: out = p0 + p1 + xn + b2s -----------------
__global__ void combine_kernel(const float* __restrict__ p0,
                               const float* __restrict__ p1,
                               const float* __restrict__ xn,
                               const float* __restrict__ b2s,
                               float* __restrict__ out, long total) {
    long i = ((long)blockIdx.x * 256 + threadIdx.x) * 4;
    if (i >= total) return;
    float4 a = *(const float4*)(p0 + i);
    float4 b = *(const float4*)(p1 + i);
    float4 c = *(const float4*)(xn + i);
    int col = (int)(i % DIMC);
    float4 s = *(const float4*)(b2s + col);
    float4 o;
    o.x = a.x + b.x + c.x + s.x;
    o.y = a.y + b.y + c.y + s.y;
    o.z = a.z + b.z + c.z + s.z;
    o.w = a.w + b.w + c.w + s.w;
    *(float4*)(out + i) = o;
}

// ---------------- LayerNorm row helper (one warp, 384 cols) -----------------
__device__ __forceinline__ void ln_row(const float* __restrict__ xr,
                                       const float* __restrict__ s,
                                       const float* __restrict__ b,
                                       __half* __restrict__ yr, int lane) {
    int c0 = lane * 2;
    float2 v[6];
    float sum = 0.f, sq = 0.f;
#pragma unroll
    for (int i = 0; i < 6; i++) {
        v[i] = *(const float2*)&xr[c0 + 64 * i];
        sum += v[i].x + v[i].y;
        sq  += v[i].x * v[i].x + v[i].y * v[i].y;
    }
#pragma unroll
    for (int o = 16; o; o >>= 1) {
        sum += __shfl_xor_sync(0xffffffffu, sum, o);
        sq  += __shfl_xor_sync(0xffffffffu, sq, o);
    }
    float mean = sum * (1.f / DIMC);
    float var  = sq * (1.f / DIMC) - mean * mean;
    float rstd = rsqrtf(var + 1e-5f);
#pragma unroll
    for (int i = 0; i < 6; i++) {
        int c = c0 + 64 * i;
        float2 sc = *(const float2*)&s[c];
        float2 bc = *(const float2*)&b[c];
        float o0 = (v[i].x - mean) * rstd * sc.x + bc.x;
        float o1 = (v[i].y - mean) * rstd * sc.y + bc.y;
        *(__half2*)&yr[c] = __floats2half2_rn(o0, o1);
    }
}

__global__ void ln_kernel(const float* __restrict__ x,
                          const float* __restrict__ s,
                          const float* __restrict__ b,
                          __half* __restrict__ y, int M) {
    int row = blockIdx.x * 8 + (threadIdx.x >> 5);
    if (row >= M) return;
    ln_row(x + (long)row * DIMC, s, b, y + (long)row * DIMC, threadIdx.x & 31);
}

// ---------------- merged prep: ln1 + transposes + convert + b2s + b2f -------
__device__ __forceinline__ void tr_tile(const float* __restrict__ src,
                                        __half* __restrict__ dst,
                                        int R, int C, int txi, int tyi, int tid) {
    __shared__ float t[32][33];
    int tx = tid & 31, ty = tid >> 5;
    int bx = txi * 32, by = tyi * 32;
#pragma unroll
    for (int i = 0; i < 32; i += 8) {
        int r = by + ty + i, c = bx + tx;
        t[ty + i][tx] = src[(long)r * C + c];
    }
    __syncthreads();
#pragma unroll
    for (int i = 0; i < 32; i += 8) {
        int r = bx + ty + i, c = by + tx;
        dst[(long)r * R + c] = __float2half(t[tx][ty + i]);
    }
}

__global__ void prep_all(const float* __restrict__ x,
                         const float* __restrict__ n1s,
                         const float* __restrict__ n1b,
                         __half* __restrict__ y, int MLN,
                         const float* __restrict__ q_w,
                         const float* __restrict__ ow,
                         const float* __restrict__ tw1,
                         const float* __restrict__ tw2,
                         const float* __restrict__ cw1,
                         const float* __restrict__ cw2,
                         const float* __restrict__ cb2,
                         const float* __restrict__ tb2,
                         const float* __restrict__ ob,
                         __half* __restrict__ qwT,
                         __half* __restrict__ owT,
                         __half* __restrict__ tw1T,
                         __half* __restrict__ tw2h,
                         __half* __restrict__ cw1T,
                         __half* __restrict__ cw2T,
                         float* __restrict__ b2s,
                         float* __restrict__ b2f) {
    const int tid = threadIdx.x;
    int blk = blockIdx.x;
    if (blk < MLN) {                          // ln1: 8 rows / block
        int row = blk * 8 + (tid >> 5);
        ln_row(x + (long)row * DIMC, n1s, n1b, y + (long)row * DIMC, tid & 31);
        return;
    }
    blk -= MLN;
    if (blk < 144) {
        tr_tile(q_w, qwT, DIMC, DIMC, blk % 12, blk / 12, tid);
    } else if (blk < 288) {
        int t = blk - 144;
        tr_tile(ow, owT, DIMC, DIMC, t % 12, t / 12, tid);
    } else if (blk < 864) {
        int t = blk - 288;
        tr_tile(tw1 + 4L * DIMC * HIDC, tw1T, DIMC, HIDC, t % 48, t / 48, tid);
    } else if (blk < 2592) {
        int t = blk - 864;
        int slab = t / 576, u = t % 576;
        tr_tile(cw1 + (long)slab * DIMC * HIDC, cw1T + (long)slab * HIDC * DIMC,
                DIMC, HIDC, u % 48, u / 48, tid);
    } else if (blk < 4320) {
        int t = blk - 2592;
        tr_tile(cw2, cw2T, 3 * HIDC, DIMC, t % 12, t / 12, tid);
    } else if (blk < 4896) {
        int t = blk - 4320;
        int idx = (t * 256 + tid) * 4;
        const float* src = tw2 + 4L * HIDC * DIMC;
        float4 v = *(const float4*)(src + idx);
        *(__half2*)(tw2h + idx)     = __floats2half2_rn(v.x, v.y);
        *(__half2*)(tw2h + idx + 2) = __floats2half2_rn(v.z, v.w);
    } else if (blk < 4898) {
        int c = (blk - 4896) * 256 + tid;
        if (c < DIMC) b2s[c] = cb2[c] + cb2[DIMC + c] + cb2[2 * DIMC + c];
    } else {                                  // b2f: warp-per-column GEMV
        int w = (blk - 4898) * 8 + (tid >> 5);
        int lane = tid & 31;
        if (w < DIMC) {
            float sum = 0.f;
#pragma unroll
            for (int i = 0; i < 12; i++) {
                int k = lane + 32 * i;
                sum += tb2[k] * ow[(long)k * DIMC + w];
            }
#pragma unroll
            for (int o = 16; o; o >>= 1) sum += __shfl_xor_sync(0xffffffffu, sum, o);
            if (lane == 0) b2f[w] = sum + ob[w];
        }
    }
}

// ---------------- launch ----------------------------------------------------
extern "C" void kernel_launch(void* const* d_in, const int* in_sizes, int n_in,
                              void* d_out, int out_size) {
    const float* x   = (const float*)d_in[0];
    const float* n1s = (const float*)d_in[1];
    const float* n1b = (const float*)d_in[2];
    const float* n2s = (const float*)d_in[3];
    const float* n2b = (const float*)d_in[4];
    const float* q_w = (const float*)d_in[5];
    const float* tw1 = (const float*)d_in[6];
    const float* tb1 = (const float*)d_in[7];
    const float* tw2 = (const float*)d_in[8];
    const float* tb2 = (const float*)d_in[9];
    const float* ow  = (const float*)d_in[10];
    const float* ob  = (const float*)d_in[11];
    const float* cw1 = (const float*)d_in[12];
    const float* cb1 = (const float*)d_in[13];
    const float* cw2 = (const float*)d_in[14];
    const float* cb2 = (const float*)d_in[15];
    const int* dT = (const int*)d_in[16];
    const int* dH = (const int*)d_in[17];
    const int* dW = (const int*)d_in[18];
    float* out = (float*)d_out;

    const int M = in_sizes[0] / DIMC;   // 16384

    __half *y, *qb, *h, *hc, *tw2h, *owT, *qwT, *tw1T, *w2fT, *cw1T, *cw2T;
    float *xn, *b2f, *b2s;
    cudaGetSymbolAddress((void**)&y,    g_y);
    cudaGetSymbolAddress((void**)&qb,   g_qb);
    cudaGetSymbolAddress((void**)&h,    g_h);
    cudaGetSymbolAddress((void**)&xn,   g_xn);
    cudaGetSymbolAddress((void**)&hc,   g_hc);
    cudaGetSymbolAddress((void**)&tw2h, g_tw2h);
    cudaGetSymbolAddress((void**)&owT,  g_owT);
    cudaGetSymbolAddress((void**)&qwT,  g_qwT);
    cudaGetSymbolAddress((void**)&tw1T, g_tw1T);
    cudaGetSymbolAddress((void**)&w2fT, g_w2fT);
    cudaGetSymbolAddress((void**)&cw1T, g_cw1T);
    cudaGetSymbolAddress((void**)&cw2T, g_cw2T);
    cudaGetSymbolAddress((void**)&b2f,  g_b2f);
    cudaGetSymbolAddress((void**)&b2s,  g_b2s);

    const int SM_S = STAGES * (64 + 128) * 128 + 1024;    // 74752  (config S)
    const int SM_F = STAGES * (128 + 128) * 128 + 1024;   // 99328  (config F)
    cudaFuncSetAttribute((tgemm<0,1,1,4,32,DIMC,DIMC>), cudaFuncAttributeMaxDynamicSharedMemorySize, SM_S);
    cudaFuncSetAttribute((tgemm<3,1,1,4,32,DIMC,DIMC>), cudaFuncAttributeMaxDynamicSharedMemorySize, SM_S);
    cudaFuncSetAttribute((tgemm<2,0,1,4,32,HIDC,HIDC>), cudaFuncAttributeMaxDynamicSharedMemorySize, SM_S);
    cudaFuncSetAttribute((tgemm<1,1,2,2,64,DIMC,DIMC>), cudaFuncAttributeMaxDynamicSharedMemorySize, SM_F);
    cudaFuncSetAttribute((tgemm<4,0,2,2,64,3*HIDC,3*HIDC>), cudaFuncAttributeMaxDynamicSharedMemorySize, SM_F);

    // ---- prep: ln1 + all weight prep fused into one kernel ----
    const int MLN = M / 8;   // 2048 ln blocks
    prep_all<<<MLN + 4946, 256>>>(x, n1s, n1b, y, MLN,
                                  q_w, ow, tw1, tw2, cw1, cw2, cb2, tb2, ob,
                                  qwT, owT, tw1T, tw2h, cw1T, cw2T, b2s, b2f);

    // w2fT = (tw2 @ ow)^T : [384,1536] = owT @ tw2h^T
    tgemm<0,1,1,4,32,DIMC,DIMC><<<dim3(HIDC / 128, DIMC / 64), 128, SM_S>>>(
        owT, tw2h, nullptr, nullptr, 0, w2fT, HIDC, DIMC,
        nullptr, nullptr, nullptr);

    // q = rope3d(LN1(x) @ q_w)
    tgemm<3,1,1,4,32,DIMC,DIMC><<<dim3(DIMC / 128, M / 64), 128, SM_S>>>(
        y, qwT, nullptr, nullptr, 0, qb, DIMC, DIMC, dT, dH, dW);

    // h = gelu(q @ titan_w1[4] + titan_b1[4])   (128x128 tile, warp 64x64)
    tgemm<1,1,2,2,64,DIMC,DIMC><<<dim3(HIDC / 128, M / 128), 128, SM_F>>>(
        qb, tw1T, tb1 + 4 * HIDC, nullptr, 0, h, HIDC, DIMC,
        nullptr, nullptr, nullptr);

    // xn = x + h @ w2f + b2f
    tgemm<2,0,1,4,32,HIDC,HIDC><<<dim3(DIMC / 128, M / 64), 128, SM_S>>>(
        h, w2fT, b2f, x, DIMC, xn, DIMC, HIDC,
        nullptr, nullptr, nullptr);

    ln_kernel<<<M / 8, 256>>>(xn, n2s, n2b, y, M);

    // hc = gelu(y @ [cw1_0|cw1_1|cw1_2] + cb1)   (128x128 tile, warp 64x64)
    tgemm<1,1,2,2,64,DIMC,DIMC><<<dim3((3 * HIDC) / 128, M / 128), 128, SM_F>>>(
        y, cw1T, cb1, nullptr, 0, hc, 3 * HIDC, DIMC,
        nullptr, nullptr, nullptr);

    // cms2 via split-K=2, F-config: partials into g_h (dead; 2x 25MB fp32)
    float* part = (float*)h;   // [2][M, 384] fp32
    tgemm<4,0,2,2,64,3*HIDC,3*HIDC><<<dim3(DIMC / 128, M / 128, 2), 128, SM_F>>>(
        hc, cw2T, nullptr, nullptr, 0, part, DIMC, (3 * HIDC) / 2,
        nullptr, nullptr, nullptr);

    // out = p0 + p1 + xn + b2s
    long total = (long)M * DIMC;
    combine_kernel<<<(int)((total / 4 + 255) / 256), 256>>>(
        part, part + total, xn, b2s, out, total);
}

// round 16
// speedup vs baseline: 1.0468x; 1.0468x over previous
#include <cuda_runtime.h>
#include <cuda_fp16.h>
#include <math.h>
#include <stdint.h>

#define DIMC 384
#define HIDC 1536
#define MMAX 16384

// ---------------- scratch (device globals; no allocation allowed) ----------
__device__ __half g_y [MMAX * DIMC];            // LN output (fp16)
__device__ __half g_qb[MMAX * DIMC];            // q after rope (fp16)
__device__ __half g_h [MMAX * HIDC];            // titan hidden (fp16)
__device__ float  g_xn[MMAX * DIMC];            // x + titan branch (fp32)
__device__ __half g_hc[(long)MMAX * 3 * HIDC];  // cms hidden concat (fp16)
__device__ __half g_tw2h[HIDC * DIMC];          // titan_w2[4] as fp16
__device__ __half g_owT [DIMC * DIMC];          // out_w^T fp16
__device__ __half g_qwT [DIMC * DIMC];          // q_w^T
__device__ __half g_tw1T[HIDC * DIMC];          // titan_w1[4]^T
__device__ __half g_w2fT[DIMC * HIDC];          // (titan_w2[4] @ out_w)^T fp16
__device__ __half g_cw1T[3L * HIDC * DIMC];     // cms_w1^T stacked [4608,384]
__device__ __half g_cw2T[(long)DIMC * 3 * HIDC];// cms_w2^T [384,4608]
__device__ float g_b2f[DIMC];
__device__ float g_b2s[DIMC];

// ---------------- helpers ---------------------------------------------------
__device__ __forceinline__ uint32_t smem_u32(const void* p) {
    uint32_t a;
    asm("{ .reg .u64 t; cvta.to.shared.u64 t, %1; cvt.u32.u64 %0, t; }"
        : "=r"(a) : "l"(p));
    return a;
}
// fast gelu: tanh formulation + tanh.approx.f32
__device__ __forceinline__ float gelu_fast(float v) {
    float u = v * (1.0f + 0.044715f * v * v) * 0.7978845608028654f;
    float t;
    asm("tanh.approx.f32 %0, %1;" : "=f"(t) : "f"(u));
    return 0.5f * v * (1.0f + t);
}
__device__ __forceinline__ void cp16(uint32_t s, const void* g) {
    asm volatile("cp.async.cg.shared.global [%0], [%1], 16;"
                 :: "r"(s), "l"(g) : "memory");
}
__device__ __forceinline__ void cp_commit() {
    asm volatile("cp.async.commit_group;" ::: "memory");
}
template <int N> __device__ __forceinline__ void cp_wait() {
    asm volatile("cp.async.wait_group %0;" :: "n"(N) : "memory");
}
__device__ __forceinline__ void ldsm4(uint32_t& r0, uint32_t& r1,
                                      uint32_t& r2, uint32_t& r3, uint32_t a) {
    asm volatile("ldmatrix.sync.aligned.m8n8.x4.shared.b16 {%0,%1,%2,%3}, [%4];"
                 : "=r"(r0), "=r"(r1), "=r"(r2), "=r"(r3) : "r"(a));
}
__device__ __forceinline__ void hmma(float* c, const uint32_t* a, const uint32_t* b) {
    asm volatile(
        "mma.sync.aligned.m16n8k16.row.col.f32.f16.f16.f32 "
        "{%0,%1,%2,%3}, {%4,%5,%6,%7}, {%8,%9}, {%0,%1,%2,%3};"
        : "+f"(c[0]), "+f"(c[1]), "+f"(c[2]), "+f"(c[3])
        : "r"(a[0]), "r"(a[1]), "r"(a[2]), "r"(a[3]), "r"(b[0]), "r"(b[1]));
}
// fp16-accumulate HMMA: D/C are 2 b32 regs (4 halves)
__device__ __forceinline__ void hmma_h(uint32_t* c, const uint32_t* a,
                                       const uint32_t* b) {
    asm volatile(
        "mma.sync.aligned.m16n8k16.row.col.f16.f16.f16.f16 "
        "{%0,%1}, {%2,%3,%4,%5}, {%6,%7}, {%0,%1};"
        : "+r"(c[0]), "+r"(c[1])
        : "r"(a[0]), "r"(a[1]), "r"(a[2]), "r"(a[3]), "r"(b[0]), "r"(b[1]));
}

#define SWZ(off) ((off) ^ (((off) >> 3) & 0x70))
#define STAGES 3

// ---------------- S-config GEMM (proven): 64x128 tile, warp 64x32 -----------
// C[M,N] = A[M,K] @ Bt[N,K]^T ; grid.x = N-blocks (fastest), grid.y = M-blocks
// EPI: 0 none, 1 gelu(+bias), 2 (+bias)(+res), 3 rope3d.  OUTH: 1 = fp16 out.
template <int EPI, int OUTH, int LDA, int LDB>
__global__ void __launch_bounds__(128, 3)
tgemm(const __half* __restrict__ A,
      const __half* __restrict__ Bt,
      const float* __restrict__ bias,
      const float* __restrict__ res, int ldres,
      void* __restrict__ Cout, int ldc, int K,
      const int* __restrict__ pT, const int* __restrict__ pH,
      const int* __restrict__ pW) {
    constexpr int BMV = 64, BNV = 128, THREADS = 128;
    constexpr int STG = (BMV + BNV) * 128;
    constexpr int ROWSTEP = THREADS / 8;
    constexpr int NA = BMV / ROWSTEP;
    constexpr int NB = BNV / ROWSTEP;
    extern __shared__ char dsm[];
    const int tid  = threadIdx.x;
    const int wid  = tid >> 5;
    const int lane = tid & 31;
    const int wn = wid;
    const uint32_t sbase = (smem_u32(dsm) + 1023u) & ~1023u;
    const uint32_t send  = sbase + 3 * STG;

    float acc[4][4][4];
#pragma unroll
    for (int i = 0; i < 4; i++)
#pragma unroll
        for (int j = 0; j < 4; j++)
#pragma unroll
            for (int k = 0; k < 4; k++) acc[i][j][k] = 0.f;

    const int lrow = tid >> 3, lc16 = tid & 7;
    const __half* pA = A  + (long)blockIdx.y * BMV * LDA + (long)lrow * LDA + lc16 * 8;
    const __half* pB = Bt + (long)blockIdx.x * BNV * LDB + (long)lrow * LDB + lc16 * 8;
    uint32_t a_soff[NA];
#pragma unroll
    for (int p = 0; p < NA; p++)
        a_soff[p] = SWZ((lrow + p * ROWSTEP) * 128 + lc16 * 16);
    uint32_t b_soff[NB];
#pragma unroll
    for (int p = 0; p < NB; p++)
        b_soff[p] = BMV * 128 + SWZ((lrow + p * ROWSTEP) * 128 + lc16 * 16);

    auto load_chunk = [&](uint32_t sb, const __half* cA, const __half* cB) {
#pragma unroll
        for (int p = 0; p < NA; p++)
            cp16(sb + a_soff[p], cA + (long)p * ROWSTEP * LDA);
#pragma unroll
        for (int p = 0; p < NB; p++)
            cp16(sb + b_soff[p], cB + (long)p * ROWSTEP * LDB);
        cp_commit();
    };

    const int nch = K >> 6;
    load_chunk(sbase, pA, pB);
    load_chunk(sbase + STG, pA + 64, pB + 64);
    pA += 128; pB += 128;
    uint32_t sb_pre = sbase + 2 * STG;
    uint32_t sA = sbase;

    const int a_row  = (lane & 7) + (((lane >> 3) & 1) << 3);
    const int a_colb = (lane >> 4) * 16;
    const int b_row  = wn * 32 + (lane & 7) + ((lane >> 4) << 3);
    const int b_colb = ((lane >> 3) & 1) * 16;
    uint32_t a_base[4], b_base[2];
#pragma unroll
    for (int mt = 0; mt < 4; mt++)
        a_base[mt] = SWZ((a_row + mt * 16) * 128 + a_colb);
#pragma unroll
    for (int nb = 0; nb < 2; nb++)
        b_base[nb] = BMV * 128 + SWZ((b_row + nb * 16) * 128 + b_colb);

    for (int c = 0; c < nch; c++) {
        if (c + STAGES - 1 < nch) cp_wait<STAGES - 2>();
        else                      cp_wait<0>();
        __syncthreads();
        if (c + STAGES - 1 < nch) {
            load_chunk(sb_pre, pA, pB);
            pA += 64; pB += 64;
            sb_pre += STG; if (sb_pre == send) sb_pre = sbase;
        }

        uint32_t aa[4], bb[2];
#pragma unroll
        for (int mt = 0; mt < 4; mt++) aa[mt] = sA + a_base[mt];
#pragma unroll
        for (int nb = 0; nb < 2; nb++) bb[nb] = sA + b_base[nb];
        sA += STG; if (sA == send) sA = sbase;

#pragma unroll
        for (int kk = 0; kk < 4; kk++) {
            const uint32_t kx = kk << 5;
            uint32_t afr[4][4];
#pragma unroll
            for (int mt = 0; mt < 4; mt++)
                ldsm4(afr[mt][0], afr[mt][1], afr[mt][2], afr[mt][3], aa[mt] ^ kx);
            uint32_t bfr[4][2];
#pragma unroll
            for (int nb = 0; nb < 2; nb++) {
                uint32_t r0, r1, r2, r3;
                ldsm4(r0, r1, r2, r3, bb[nb] ^ kx);
                bfr[nb * 2][0] = r0; bfr[nb * 2][1] = r1;
                bfr[nb * 2 + 1][0] = r2; bfr[nb * 2 + 1][1] = r3;
            }
#pragma unroll
            for (int mt = 0; mt < 4; mt++)
#pragma unroll
                for (int nt = 0; nt < 4; nt++)
                    hmma(acc[mt][nt], afr[mt], bfr[nt]);
        }
    }

    const int g = lane >> 2, tig = lane & 3;
    const long row0 = (long)blockIdx.y * BMV;
    const int colb  = blockIdx.x * BNV + wn * 32;
    float* Cf = (float*)Cout;
    __half* Ch = (__half*)Cout;

    int rT = 0, rH = 0, rW = 0;
    if (EPI == 3) { rT = __ldg(pT); rH = __ldg(pH); rW = __ldg(pW); }

#pragma unroll
    for (int mt = 0; mt < 4; mt++) {
#pragma unroll
        for (int h = 0; h < 2; h++) {
            long row = row0 + mt * 16 + g + h * 8;
            float tp = 0.f, hp = 0.f, wp = 0.f;
            if (EPI == 3) {
                int Nn = rT * rH * rW;
                int n = (int)(row % Nn);
                int HW = rH * rW;
                tp = (float)(n / HW);
                int rem = n % HW;
                hp = (float)(rem / rW);
                wp = (float)(rem % rW);
            }
#pragma unroll
            for (int nt = 0; nt < 4; nt++) {
                int col = colb + nt * 8 + tig * 2;
                float v0 = acc[mt][nt][2 * h];
                float v1 = acc[mt][nt][2 * h + 1];
                if (EPI == 1 || EPI == 2) {
                    float2 bv = *(const float2*)(bias + col);
                    v0 += bv.x; v1 += bv.y;
                }
                if (EPI == 1) { v0 = gelu_fast(v0); v1 = gelu_fast(v1); }
                if (EPI == 2) {
                    float2 r = *(const float2*)(res + row * (long)ldres + col);
                    v0 += r.x; v1 += r.y;
                }
                if (EPI == 3) {
                    int hd = col % 24;
                    int ch = hd >> 3;
                    int jj = (hd & 7) >> 1;
                    float pos = (ch == 0) ? tp : ((ch == 1) ? hp : wp);
                    const float tbl[4] = {1.0f, 0.1f, 0.01f, 0.001f};
                    float ang = pos * tbl[jj];
                    float sn, cs;
                    sincosf(ang, &sn, &cs);
                    float n0 = v0 * cs - v1 * sn;
                    float n1 = v0 * sn + v1 * cs;
                    v0 = n0; v1 = n1;
                }
                if (OUTH) {
                    __half2 t = __floats2half2_rn(v0, v1);
                    *(__half2*)(Ch + row * (long)ldc + col) = t;
                } else {
                    *(float2*)(Cf + row * (long)ldc + col) = make_float2(v0, v1);
                }
            }
        }
    }
}

// ---------------- gelu GEMM, fp16 accumulators, 3 CTAs/SM -------------------
// C[M,N] = gelu(A[M,384] @ Bt[N,384]^T + bias), fp16 out.
// 128x128 tile, warps 2x2, warp tile 64x64, 2-stage cp.async, 128 threads.
// fp16 acc halves accumulator regs -> 3 CTAs/SM (9 warps more latency hiding).
__global__ void __launch_bounds__(128, 3)
tgemm_h(const __half* __restrict__ A,
        const __half* __restrict__ Bt,
        const float* __restrict__ bias,
        __half* __restrict__ Cout, int ldc) {
    constexpr int LDA = DIMC, LDB = DIMC;
    constexpr int NCH = DIMC / 64;              // 6 chunks
    constexpr int STG = 256 * 128;              // 32KB per stage
    extern __shared__ char dsm[];
    const int tid  = threadIdx.x;
    const int wid  = tid >> 5;
    const int lane = tid & 31;
    const int wm = wid >> 1;                    // 2 warps along M
    const int wn = wid & 1;                     // 2 warps along N
    const uint32_t sbase = (smem_u32(dsm) + 1023u) & ~1023u;

    uint32_t hacc[4][8][2];
#pragma unroll
    for (int i = 0; i < 4; i++)
#pragma unroll
        for (int j = 0; j < 8; j++) { hacc[i][j][0] = 0u; hacc[i][j][1] = 0u; }

    const int lrow = tid >> 3, lc16 = tid & 7;
    const __half* pA = A  + (long)blockIdx.y * 128 * LDA + (long)lrow * LDA + lc16 * 8;
    const __half* pB = Bt + (long)blockIdx.x * 128 * LDB + (long)lrow * LDB + lc16 * 8;
    uint32_t a_soff[8], b_soff[8];
#pragma unroll
    for (int p = 0; p < 8; p++) {
        a_soff[p] = SWZ((lrow + p * 16) * 128 + lc16 * 16);
        b_soff[p] = 128 * 128 + SWZ((lrow + p * 16) * 128 + lc16 * 16);
    }

    auto load_chunk = [&](uint32_t sb, const __half* cA, const __half* cB) {
#pragma unroll
        for (int p = 0; p < 8; p++)
            cp16(sb + a_soff[p], cA + (long)p * 16 * LDA);
#pragma unroll
        for (int p = 0; p < 8; p++)
            cp16(sb + b_soff[p], cB + (long)p * 16 * LDB);
        cp_commit();
    };

    load_chunk(sbase, pA, pB);
    load_chunk(sbase + STG, pA + 64, pB + 64);
    pA += 128; pB += 128;

    const int a_row  = wm * 64 + (lane & 7) + (((lane >> 3) & 1) << 3);
    const int a_colb = (lane >> 4) * 16;
    const int b_row  = wn * 64 + (lane & 7) + ((lane >> 4) << 3);
    const int b_colb = ((lane >> 3) & 1) * 16;
    uint32_t a_base[4], b_base[4];
#pragma unroll
    for (int mt = 0; mt < 4; mt++)
        a_base[mt] = SWZ((a_row + mt * 16) * 128 + a_colb);
#pragma unroll
    for (int nb = 0; nb < 4; nb++)
        b_base[nb] = 128 * 128 + SWZ((b_row + nb * 16) * 128 + b_colb);

    for (int c = 0; c < NCH; c++) {
        if (c + 1 < NCH) cp_wait<1>();
        else             cp_wait<0>();
        __syncthreads();

        uint32_t sA = sbase + (c & 1) * STG;
        uint32_t aa[4], bb[4];
#pragma unroll
        for (int mt = 0; mt < 4; mt++) aa[mt] = sA + a_base[mt];
#pragma unroll
        for (int nb = 0; nb < 4; nb++) bb[nb] = sA + b_base[nb];

#pragma unroll
        for (int kk = 0; kk < 4; kk++) {
            const uint32_t kx = kk << 5;
            uint32_t afr[4][4];
#pragma unroll
            for (int mt = 0; mt < 4; mt++)
                ldsm4(afr[mt][0], afr[mt][1], afr[mt][2], afr[mt][3], aa[mt] ^ kx);
            uint32_t bfr[8][2];
#pragma unroll
            for (int nb = 0; nb < 4; nb++) {
                uint32_t r0, r1, r2, r3;
                ldsm4(r0, r1, r2, r3, bb[nb] ^ kx);
                bfr[nb * 2][0] = r0; bfr[nb * 2][1] = r1;
                bfr[nb * 2 + 1][0] = r2; bfr[nb * 2 + 1][1] = r3;
            }
#pragma unroll
            for (int mt = 0; mt < 4; mt++)
#pragma unroll
                for (int nt = 0; nt < 8; nt++)
                    hmma_h(hacc[mt][nt], afr[mt], bfr[nt]);
        }

        if (c + 2 < NCH) {
            __syncthreads();    // all warps done reading this buffer
            load_chunk(sA, pA, pB);
            pA += 64; pB += 64;
        }
    }

    // ---- epilogue: gelu(+bias), fp16 out ----
    const int g = lane >> 2, tig = lane & 3;
    const long row0 = (long)blockIdx.y * 128 + wm * 64;
    const int colb  = blockIdx.x * 128 + wn * 64;

#pragma unroll
    for (int mt = 0; mt < 4; mt++) {
#pragma unroll
        for (int h = 0; h < 2; h++) {
            long row = row0 + mt * 16 + g + h * 8;
#pragma unroll
            for (int nt = 0; nt < 8; nt++) {
                int col = colb + nt * 8 + tig * 2;
                float2 bv = *(const float2*)(bias + col);
                __half2 hv = *(__half2*)&hacc[mt][nt][h];
                float v0 = gelu_fast(__low2float(hv)  + bv.x);
                float v1 = gelu_fast(__high2float(hv) + bv.y);
                __half2 t = __floats2half2_rn(v0, v1);
                *(__half2*)(Cout + row * (long)ldc + col) = t;
            }
        }
    }
}

// ---------------- LayerNorm row helper (one warp, 384 cols) -----------------
__device__ __forceinline__ void ln_row(const float* __restrict__ xr,
                                       const float* __restrict__ s,
                                       const float* __restrict__ b,
                                       __half* __restrict__ yr, int lane) {
    int c0 = lane * 2;
    float2 v[6];
    float sum = 0.f, sq = 0.f;
#pragma unroll
    for (int i = 0; i < 6; i++) {
        v[i] = *(const float2*)&xr[c0 + 64 * i];
        sum += v[i].x + v[i].y;
        sq  += v[i].x * v[i].x + v[i].y * v[i].y;
    }
#pragma unroll
    for (int o = 16; o; o >>= 1) {
        sum += __shfl_xor_sync(0xffffffffu, sum, o);
        sq  += __shfl_xor_sync(0xffffffffu, sq, o);
    }
    float mean = sum * (1.f / DIMC);
    float var  = sq * (1.f / DIMC) - mean * mean;
    float rstd = rsqrtf(var + 1e-5f);
#pragma unroll
    for (int i = 0; i < 6; i++) {
        int c = c0 + 64 * i;
        float2 sc = *(const float2*)&s[c];
        float2 bc = *(const float2*)&b[c];
        float o0 = (v[i].x - mean) * rstd * sc.x + bc.x;
        float o1 = (v[i].y - mean) * rstd * sc.y + bc.y;
        *(__half2*)&yr[c] = __floats2half2_rn(o0, o1);
    }
}

__global__ void ln_kernel(const float* __restrict__ x,
                          const float* __restrict__ s,
                          const float* __restrict__ b,
                          __half* __restrict__ y, int M) {
    int row = blockIdx.x * 8 + (threadIdx.x >> 5);
    if (row >= M) return;
    ln_row(x + (long)row * DIMC, s, b, y + (long)row * DIMC, threadIdx.x & 31);
}

// ---------------- merged prep: ln1 + transposes + convert + b2s + b2f -------
__device__ __forceinline__ void tr_tile(const float* __restrict__ src,
                                        __half* __restrict__ dst,
                                        int R, int C, int txi, int tyi, int tid) {
    __shared__ float t[32][33];
    int tx = tid & 31, ty = tid >> 5;
    int bx = txi * 32, by = tyi * 32;
#pragma unroll
    for (int i = 0; i < 32; i += 8) {
        int r = by + ty + i, c = bx + tx;
        t[ty + i][tx] = src[(long)r * C + c];
    }
    __syncthreads();
#pragma unroll
    for (int i = 0; i < 32; i += 8) {
        int r = bx + ty + i, c = by + tx;
        dst[(long)r * R + c] = __float2half(t[tx][ty + i]);
    }
}

__global__ void prep_all(const float* __restrict__ x,
                         const float* __restrict__ n1s,
                         const float* __restrict__ n1b,
                         __half* __restrict__ y, int MLN,
                         const float* __restrict__ q_w,
                         const float* __restrict__ ow,
                         const float* __restrict__ tw1,
                         const float* __restrict__ tw2,
                         const float* __restrict__ cw1,
                         const float* __restrict__ cw2,
                         const float* __restrict__ cb2,
                         const float* __restrict__ tb2,
                         const float* __restrict__ ob,
                         __half* __restrict__ qwT,
                         __half* __restrict__ owT,
                         __half* __restrict__ tw1T,
                         __half* __restrict__ tw2h,
                         __half* __restrict__ cw1T,
                         __half* __restrict__ cw2T,
                         float* __restrict__ b2s,
                         float* __restrict__ b2f) {
    const int tid = threadIdx.x;
    int blk = blockIdx.x;
    if (blk < MLN) {
        int row = blk * 8 + (tid >> 5);
        ln_row(x + (long)row * DIMC, n1s, n1b, y + (long)row * DIMC, tid & 31);
        return;
    }
    blk -= MLN;
    if (blk < 144) {
        tr_tile(q_w, qwT, DIMC, DIMC, blk % 12, blk / 12, tid);
    } else if (blk < 288) {
        int t = blk - 144;
        tr_tile(ow, owT, DIMC, DIMC, t % 12, t / 12, tid);
    } else if (blk < 864) {
        int t = blk - 288;
        tr_tile(tw1 + 4L * DIMC * HIDC, tw1T, DIMC, HIDC, t % 48, t / 48, tid);
    } else if (blk < 2592) {
        int t = blk - 864;
        int slab = t / 576, u = t % 576;
        tr_tile(cw1 + (long)slab * DIMC * HIDC, cw1T + (long)slab * HIDC * DIMC,
                DIMC, HIDC, u % 48, u / 48, tid);
    } else if (blk < 4320) {
        int t = blk - 2592;
        tr_tile(cw2, cw2T, 3 * HIDC, DIMC, t % 12, t / 12, tid);
    } else if (blk < 4896) {
        int t = blk - 4320;
        int idx = (t * 256 + tid) * 4;
        const float* src = tw2 + 4L * HIDC * DIMC;
        float4 v = *(const float4*)(src + idx);
        *(__half2*)(tw2h + idx)     = __floats2half2_rn(v.x, v.y);
        *(__half2*)(tw2h + idx + 2) = __floats2half2_rn(v.z, v.w);
    } else if (blk < 4898) {
        int c = (blk - 4896) * 256 + tid;
        if (c < DIMC) b2s[c] = cb2[c] + cb2[DIMC + c] + cb2[2 * DIMC + c];
    } else {
        int w = (blk - 4898) * 8 + (tid >> 5);
        int lane = tid & 31;
        if (w < DIMC) {
            float sum = 0.f;
#pragma unroll
            for (int i = 0; i < 12; i++) {
                int k = lane + 32 * i;
                sum += tb2[k] * ow[(long)k * DIMC + w];
            }
#pragma unroll
            for (int o = 16; o; o >>= 1) sum += __shfl_xor_sync(0xffffffffu, sum, o);
            if (lane == 0) b2f[w] = sum + ob[w];
        }
    }
}

// ---------------- launch ----------------------------------------------------
extern "C" void kernel_launch(void* const* d_in, const int* in_sizes, int n_in,
                              void* d_out, int out_size) {
    const float* x   = (const float*)d_in[0];
    const float* n1s = (const float*)d_in[1];
    const float* n1b = (const float*)d_in[2];
    const float* n2s = (const float*)d_in[3];
    const float* n2b = (const float*)d_in[4];
    const float* q_w = (const float*)d_in[5];
    const float* tw1 = (const float*)d_in[6];
    const float* tb1 = (const float*)d_in[7];
    const float* tw2 = (const float*)d_in[8];
    const float* tb2 = (const float*)d_in[9];
    const float* ow  = (const float*)d_in[10];
    const float* ob  = (const float*)d_in[11];
    const float* cw1 = (const float*)d_in[12];
    const float* cb1 = (const float*)d_in[13];
    const float* cw2 = (const float*)d_in[14];
    const float* cb2 = (const float*)d_in[15];
    const int* dT = (const int*)d_in[16];
    const int* dH = (const int*)d_in[17];
    const int* dW = (const int*)d_in[18];
    float* out = (float*)d_out;

    const int M = in_sizes[0] / DIMC;   // 16384

    __half *y, *qb, *h, *hc, *tw2h, *owT, *qwT, *tw1T, *w2fT, *cw1T, *cw2T;
    float *xn, *b2f, *b2s;
    cudaGetSymbolAddress((void**)&y,    g_y);
    cudaGetSymbolAddress((void**)&qb,   g_qb);
    cudaGetSymbolAddress((void**)&h,    g_h);
    cudaGetSymbolAddress((void**)&xn,   g_xn);
    cudaGetSymbolAddress((void**)&hc,   g_hc);
    cudaGetSymbolAddress((void**)&tw2h, g_tw2h);
    cudaGetSymbolAddress((void**)&owT,  g_owT);
    cudaGetSymbolAddress((void**)&qwT,  g_qwT);
    cudaGetSymbolAddress((void**)&tw1T, g_tw1T);
    cudaGetSymbolAddress((void**)&w2fT, g_w2fT);
    cudaGetSymbolAddress((void**)&cw1T, g_cw1T);
    cudaGetSymbolAddress((void**)&cw2T, g_cw2T);
    cudaGetSymbolAddress((void**)&b2f,  g_b2f);
    cudaGetSymbolAddress((void**)&b2s,  g_b2s);

    const int SM_S = STAGES * (64 + 128) * 128 + 1024;    // 74752
    const int SM_H = 2 * 256 * 128 + 1024;                // 66560 (2-stage)
    cudaFuncSetAttribute((tgemm<0,1,DIMC,DIMC>), cudaFuncAttributeMaxDynamicSharedMemorySize, SM_S);
    cudaFuncSetAttribute((tgemm<3,1,DIMC,DIMC>), cudaFuncAttributeMaxDynamicSharedMemorySize, SM_S);
    cudaFuncSetAttribute((tgemm<2,0,HIDC,HIDC>), cudaFuncAttributeMaxDynamicSharedMemorySize, SM_S);
    cudaFuncSetAttribute((tgemm<2,0,3*HIDC,3*HIDC>), cudaFuncAttributeMaxDynamicSharedMemorySize, SM_S);
    cudaFuncSetAttribute(tgemm_h, cudaFuncAttributeMaxDynamicSharedMemorySize, SM_H);

    // ---- prep: ln1 + all weight prep fused into one kernel ----
    const int MLN = M / 8;
    prep_all<<<MLN + 4946, 256>>>(x, n1s, n1b, y, MLN,
                                  q_w, ow, tw1, tw2, cw1, cw2, cb2, tb2, ob,
                                  qwT, owT, tw1T, tw2h, cw1T, cw2T, b2s, b2f);

    // w2fT = (tw2 @ ow)^T : [384,1536] = owT @ tw2h^T
    tgemm<0,1,DIMC,DIMC><<<dim3(HIDC / 128, DIMC / 64), 128, SM_S>>>(
        owT, tw2h, nullptr, nullptr, 0, w2fT, HIDC, DIMC,
        nullptr, nullptr, nullptr);

    // q = rope3d(LN1(x) @ q_w)
    tgemm<3,1,DIMC,DIMC><<<dim3(DIMC / 128, M / 64), 128, SM_S>>>(
        y, qwT, nullptr, nullptr, 0, qb, DIMC, DIMC, dT, dH, dW);

    // h = gelu(q @ titan_w1[4] + titan_b1[4])   (fp16-acc, 3 CTAs/SM)
    tgemm_h<<<dim3(HIDC / 128, M / 128), 128, SM_H>>>(
        qb, tw1T, tb1 + 4 * HIDC, h, HIDC);

    // xn = x + h @ w2f + b2f
    tgemm<2,0,HIDC,HIDC><<<dim3(DIMC / 128, M / 64), 128, SM_S>>>(
        h, w2fT, b2f, x, DIMC, xn, DIMC, HIDC,
        nullptr, nullptr, nullptr);

    ln_kernel<<<M / 8, 256>>>(xn, n2s, n2b, y, M);

    // hc = gelu(y @ [cw1_0|cw1_1|cw1_2] + cb1)   (fp16-acc, 3 CTAs/SM)
    tgemm_h<<<dim3((3 * HIDC) / 128, M / 128), 128, SM_H>>>(
        y, cw1T, cb1, hc, 3 * HIDC);

    // out = xn + hc @ cw2 + b2s
    tgemm<2,0,3*HIDC,3*HIDC><<<dim3(DIMC / 128, M / 64), 128, SM_S>>>(
        hc, cw2T, b2s, xn, DIMC, out, DIMC, 3 * HIDC,
        nullptr, nullptr, nullptr);
}